// round 1
// baseline (speedup 1.0000x reference)
#include <cuda_runtime.h>

#define B_  16
#define Q_  1000
#define N_  16
#define C_  256
#define H_  100
#define W_  100
#define HW_ 10000
#define NH_ 8
#define D_  32
#define TQ  8      // queries per block
#define AP  260    // A_sm row pitch (floats): 16B-aligned, conflict-staggered

// smem layout (floats):
//  q_sm   [TQ*C_]        = 2048
//  qp_sm  [TQ*C_]        = 2048
//  tm_sm  [TQ*NH_*C_]    = 16384   (t, then reused as m)
//  A_sm   [TQ*N_*AP]     = 33280
//  sc_sm  [TQ*NH_*N_]    = 1024
//  at_sm  [TQ*N_*NH_]    = 1024    (attn transposed [i][j][h])
//  u_sm   [TQ*NH_]       = 64
#define SMEM_FLOATS (2048 + 2048 + 16384 + 33280 + 1024 + 1024 + 64)
#define SMEM_BYTES  (SMEM_FLOATS * 4)

// channels-last copy of x: [B,H,W,C]  (163.84 MB static scratch)
__device__ float g_xt[B_ * HW_ * C_];

// ---------------------------------------------------------------------------
// Kernel 1: transpose x [B,C,HW] -> g_xt [B,HW,C]
// ---------------------------------------------------------------------------
__global__ void transpose_x_kernel(const float* __restrict__ x) {
    __shared__ float tile[32][33];
    int b  = blockIdx.z;
    int p0 = blockIdx.x * 32;   // HW dim
    int c0 = blockIdx.y * 32;   // C dim
    int tx = threadIdx.x;
    int ty = threadIdx.y;       // 32x8 threads

    #pragma unroll
    for (int dy = 0; dy < 32; dy += 8) {
        int c = c0 + ty + dy;
        int p = p0 + tx;
        float v = 0.f;
        if (p < HW_) v = x[(size_t)(b * C_ + c) * HW_ + p];
        tile[ty + dy][tx] = v;
    }
    __syncthreads();
    #pragma unroll
    for (int dy = 0; dy < 32; dy += 8) {
        int p = p0 + ty + dy;
        int c = c0 + tx;
        if (p < HW_) g_xt[(size_t)(b * HW_ + p) * C_ + c] = tile[tx][ty + dy];
    }
}

// ---------------------------------------------------------------------------
// Kernel 2: fused deformable attention. One block = TQ queries of one batch.
// ---------------------------------------------------------------------------
__global__ __launch_bounds__(256, 1)
void deform_attn_kernel(const float* __restrict__ q,
                        const float* __restrict__ ref,
                        const float* __restrict__ wq, const float* __restrict__ bq,
                        const float* __restrict__ wk, const float* __restrict__ bk,
                        const float* __restrict__ wv, const float* __restrict__ bv,
                        float* __restrict__ out) {
    extern __shared__ float sm[];
    float* q_sm  = sm;                       // TQ*256
    float* qp_sm = q_sm  + TQ * C_;          // TQ*256
    float* tm_sm = qp_sm + TQ * C_;          // TQ*8*256  (t then m)
    float* A_sm  = tm_sm + TQ * NH_ * C_;    // TQ*16*AP
    float* sc_sm = A_sm  + TQ * N_ * AP;     // TQ*8*16
    float* at_sm = sc_sm + TQ * NH_ * N_;    // TQ*16*8
    float* u_sm  = at_sm + TQ * N_ * NH_;    // TQ*8

    const int tid = threadIdx.x;
    const int b   = blockIdx.y;
    const int gq0 = blockIdx.x * TQ;

    // ---- load q rows for TQ queries ----
    for (int idx = tid; idx < TQ * C_; idx += 256)
        q_sm[idx] = q[(size_t)(b * Q_ + gq0 + idx / C_) * C_ + (idx % C_)];
    __syncthreads();

    // ---- qp = q @ wq^T + bq : thread owns output channel c ----
    {
        const int c = tid;
        float acc[TQ];
        #pragma unroll
        for (int i = 0; i < TQ; i++) acc[i] = 0.f;
        const float4* wrow = (const float4*)(wq + (size_t)c * C_);
        for (int k4 = 0; k4 < C_ / 4; k4++) {
            float4 w = __ldg(wrow + k4);
            #pragma unroll
            for (int i = 0; i < TQ; i++) {
                float4 qv = *(const float4*)(q_sm + i * C_ + k4 * 4);
                acc[i] += qv.x * w.x + qv.y * w.y + qv.z * w.z + qv.w * w.w;
            }
        }
        float bb = __ldg(bq + c);
        #pragma unroll
        for (int i = 0; i < TQ; i++) qp_sm[i * C_ + c] = acc[i] + bb;
    }
    __syncthreads();

    // ---- t[i][h][k] = sum_dd qp[i][h*32+dd] * wk[h*32+dd][k] : thread owns k ----
    {
        const int k = tid;
        for (int h = 0; h < NH_; h++) {
            float acc[TQ];
            #pragma unroll
            for (int i = 0; i < TQ; i++) acc[i] = 0.f;
            #pragma unroll 4
            for (int d4 = 0; d4 < D_ / 4; d4++) {
                const float* wp = wk + (size_t)(h * D_ + d4 * 4) * C_ + k;
                float w0 = __ldg(wp);
                float w1 = __ldg(wp + C_);
                float w2 = __ldg(wp + 2 * C_);
                float w3 = __ldg(wp + 3 * C_);
                #pragma unroll
                for (int i = 0; i < TQ; i++) {
                    float4 qv = *(const float4*)(qp_sm + i * C_ + h * D_ + d4 * 4);
                    acc[i] += qv.x * w0 + qv.y * w1 + qv.z * w2 + qv.w * w3;
                }
            }
            #pragma unroll
            for (int i = 0; i < TQ; i++) tm_sm[(i * NH_ + h) * C_ + k] = acc[i];
        }
    }
    // ---- u[i][h] = qp_head . bk_head ----
    if (tid < TQ * NH_) {
        int i = tid / NH_, h = tid % NH_;
        float s = 0.f;
        #pragma unroll
        for (int dd = 0; dd < D_; dd++)
            s += qp_sm[i * C_ + h * D_ + dd] * __ldg(bk + h * D_ + dd);
        u_sm[tid] = s;
    }

    // ---- gather: A[i][j][k] = bilinear sample of x at (b, q=rr%1000, n=rr/1000) ----
    {
        const int k = tid;
        for (int row = 0; row < TQ * N_; row++) {
            int i  = row >> 4, j = row & 15;
            int rr = (gq0 + i) * N_ + j;
            int n  = rr / Q_;
            int qq = rr - n * Q_;
            float2 g = __ldg((const float2*)(ref + (size_t)((b * Q_ + qq) * N_ + n) * 2));
            float gx = ((g.x + 1.0f) * (float)W_ - 1.0f) * 0.5f;
            float gy = ((g.y + 1.0f) * (float)H_ - 1.0f) * 0.5f;
            float x0f = floorf(gx), y0f = floorf(gy);
            float fx = gx - x0f, fy = gy - y0f;
            int x0 = (int)x0f, y0 = (int)y0f;
            int x1 = x0 + 1,   y1 = y0 + 1;
            bool vx0 = (x0 >= 0) & (x0 < W_);
            bool vx1 = (x1 >= 0) & (x1 < W_);
            bool vy0 = (y0 >= 0) & (y0 < H_);
            bool vy1 = (y1 >= 0) & (y1 < H_);
            const float* xb = g_xt + (size_t)b * HW_ * C_;
            float val = 0.f;
            if (vy0) {
                const float* rp = xb + (size_t)(y0 * W_) * C_;
                if (vx0) val += (1.f - fx) * (1.f - fy) * __ldg(rp + (size_t)x0 * C_ + k);
                if (vx1) val += fx * (1.f - fy)         * __ldg(rp + (size_t)x1 * C_ + k);
            }
            if (vy1) {
                const float* rp = xb + (size_t)(y1 * W_) * C_;
                if (vx0) val += (1.f - fx) * fy * __ldg(rp + (size_t)x0 * C_ + k);
                if (vx1) val += fx * fy         * __ldg(rp + (size_t)x1 * C_ + k);
            }
            A_sm[row * AP + k] = val;
        }
    }
    __syncthreads();

    // ---- scores[i][h][j] = (A[i][j][:] . t[i][h][:] + u[i][h]) / sqrt(d) ----
    if (tid < TQ * N_) {   // 128 threads: (i,j)
        int i = tid >> 4, j = tid & 15;
        float acc[NH_];
        #pragma unroll
        for (int h = 0; h < NH_; h++) acc[h] = 0.f;
        const float4* arow = (const float4*)(A_sm + (i * N_ + j) * AP);
        for (int k4 = 0; k4 < C_ / 4; k4++) {
            float4 a = arow[k4];
            #pragma unroll
            for (int h = 0; h < NH_; h++) {
                float4 t4 = *(const float4*)(tm_sm + (i * NH_ + h) * C_ + k4 * 4);
                acc[h] += a.x * t4.x + a.y * t4.y + a.z * t4.z + a.w * t4.w;
            }
        }
        const float scale = 0.17677669529663687f; // 1/sqrt(32)
        #pragma unroll
        for (int h = 0; h < NH_; h++)
            sc_sm[(i * NH_ + h) * N_ + j] = (acc[h] + u_sm[i * NH_ + h]) * scale;
    }
    __syncthreads();

    // ---- softmax over j (16) per (i,h) ----
    if (tid < TQ * NH_) {  // 64 threads
        int i = tid >> 3, h = tid & 7;
        float s[N_];
        float mx = -1e30f;
        #pragma unroll
        for (int j = 0; j < N_; j++) {
            s[j] = sc_sm[(i * NH_ + h) * N_ + j];
            mx = fmaxf(mx, s[j]);
        }
        float sum = 0.f;
        #pragma unroll
        for (int j = 0; j < N_; j++) { s[j] = expf(s[j] - mx); sum += s[j]; }
        float inv = 1.f / sum;
        #pragma unroll
        for (int j = 0; j < N_; j++)
            at_sm[(i * N_ + j) * NH_ + h] = s[j] * inv;
    }
    __syncthreads();

    // ---- m[i][h][k] = sum_j attn[i][h][j] * A[i][j][k] : thread owns k, overwrite tm ----
    {
        const int k = tid;
        for (int i = 0; i < TQ; i++) {
            float acc[NH_];
            #pragma unroll
            for (int h = 0; h < NH_; h++) acc[h] = 0.f;
            #pragma unroll
            for (int j = 0; j < N_; j++) {
                float a = A_sm[(i * N_ + j) * AP + k];
                float4 w0 = *(const float4*)(at_sm + (i * N_ + j) * NH_);
                float4 w1 = *(const float4*)(at_sm + (i * N_ + j) * NH_ + 4);
                acc[0] += a * w0.x; acc[1] += a * w0.y;
                acc[2] += a * w0.z; acc[3] += a * w0.w;
                acc[4] += a * w1.x; acc[5] += a * w1.y;
                acc[6] += a * w1.z; acc[7] += a * w1.w;
            }
            #pragma unroll
            for (int h = 0; h < NH_; h++) tm_sm[(i * NH_ + h) * C_ + k] = acc[h];
        }
    }
    __syncthreads();

    // ---- out[i][c] = sum_k m[i][h(c)][k] * wv[c][k] + bv[c] : thread owns c ----
    {
        const int c = tid;
        const int h = c >> 5;
        float acc[TQ];
        float bb = __ldg(bv + c);
        #pragma unroll
        for (int i = 0; i < TQ; i++) acc[i] = bb;
        const float4* wrow = (const float4*)(wv + (size_t)c * C_);
        for (int k4 = 0; k4 < C_ / 4; k4++) {
            float4 w = __ldg(wrow + k4);
            #pragma unroll
            for (int i = 0; i < TQ; i++) {
                float4 m4 = *(const float4*)(tm_sm + (i * NH_ + h) * C_ + k4 * 4);
                acc[i] += m4.x * w.x + m4.y * w.y + m4.z * w.z + m4.w * w.w;
            }
        }
        #pragma unroll
        for (int i = 0; i < TQ; i++)
            out[(size_t)(b * Q_ + gq0 + i) * C_ + c] = acc[i];
    }
}

// ---------------------------------------------------------------------------
extern "C" void kernel_launch(void* const* d_in, const int* in_sizes, int n_in,
                              void* d_out, int out_size) {
    const float* x   = (const float*)d_in[0];
    const float* q   = (const float*)d_in[1];
    const float* ref = (const float*)d_in[2];
    const float* wq  = (const float*)d_in[3];
    const float* bq  = (const float*)d_in[4];
    const float* wk  = (const float*)d_in[5];
    const float* bk  = (const float*)d_in[6];
    const float* wv  = (const float*)d_in[7];
    const float* bv  = (const float*)d_in[8];
    float* out = (float*)d_out;

    (void)in_sizes; (void)n_in; (void)out_size;

    // transpose x -> channels-last scratch
    dim3 tg((HW_ + 31) / 32, C_ / 32, B_);
    transpose_x_kernel<<<tg, dim3(32, 8)>>>(x);

    // fused attention
    cudaFuncSetAttribute(deform_attn_kernel,
                         cudaFuncAttributeMaxDynamicSharedMemorySize, SMEM_BYTES);
    deform_attn_kernel<<<dim3(Q_ / TQ, B_), 256, SMEM_BYTES>>>(
        q, ref, wq, bq, wk, bk, wv, bv, out);
}

// round 2
// speedup vs baseline: 1.5382x; 1.5382x over previous
#include <cuda_runtime.h>

#define B_  16
#define Q_  1000
#define N_  16
#define C_  256
#define H_  100
#define W_  100
#define HW_ 10000
#define NH_ 8
#define D_  32
#define TQ  8      // queries per block
#define AP  260    // A_sm row pitch (floats)
#define NTHREADS 512

// smem layout (floats):
//  q_sm   [TQ*C_]        = 2048
//  qp_sm  [TQ*C_]        = 2048
//  tm_sm  [TQ*NH_*C_]    = 16384   (t, then reused as m)
//  A_sm   [TQ*N_*AP]     = 33280
//  sc_sm  [TQ*NH_*N_]    = 1024
//  at_sm  [TQ*N_*NH_]    = 1024    (attn transposed [i][j][h])
//  u_sm   [TQ*NH_]       = 64
//  wt_sm  [TQ*N_*4]      = 512     (bilinear weights per row, float4)
//  off_sm [TQ*N_*4]      = 512     (tap base offsets per row, int4; -1 = invalid)
#define SMEM_FLOATS (2048 + 2048 + 16384 + 33280 + 1024 + 1024 + 64 + 512 + 512)
#define SMEM_BYTES  (SMEM_FLOATS * 4)

// channels-last copy of x: [B,H,W,C]
__device__ float g_xt[B_ * HW_ * C_];

// ---------------------------------------------------------------------------
// Kernel 1: transpose x [B,C,HW] -> g_xt [B,HW,C]
// ---------------------------------------------------------------------------
__global__ void transpose_x_kernel(const float* __restrict__ x) {
    __shared__ float tile[32][33];
    int b  = blockIdx.z;
    int p0 = blockIdx.x * 32;   // HW dim
    int c0 = blockIdx.y * 32;   // C dim
    int tx = threadIdx.x;
    int ty = threadIdx.y;       // 32x8 threads

    #pragma unroll
    for (int dy = 0; dy < 32; dy += 8) {
        int c = c0 + ty + dy;
        int p = p0 + tx;
        float v = 0.f;
        if (p < HW_) v = x[(size_t)(b * C_ + c) * HW_ + p];
        tile[ty + dy][tx] = v;
    }
    __syncthreads();
    #pragma unroll
    for (int dy = 0; dy < 32; dy += 8) {
        int p = p0 + ty + dy;
        int c = c0 + tx;
        if (p < HW_) g_xt[(size_t)(b * HW_ + p) * C_ + c] = tile[tx][ty + dy];
    }
}

// ---------------------------------------------------------------------------
// Kernel 2: fused deformable attention. One block = TQ queries of one batch.
// 512 threads. Warps 0-7: projections. Warps 8-15: bilinear gather.
// ---------------------------------------------------------------------------
__global__ __launch_bounds__(NTHREADS, 1)
void deform_attn_kernel(const float* __restrict__ q,
                        const float* __restrict__ ref,
                        const float* __restrict__ wq, const float* __restrict__ bq,
                        const float* __restrict__ wk, const float* __restrict__ bk,
                        const float* __restrict__ wv, const float* __restrict__ bv,
                        float* __restrict__ out) {
    extern __shared__ float sm[];
    float* q_sm  = sm;                        // TQ*256
    float* qp_sm = q_sm  + TQ * C_;           // TQ*256
    float* tm_sm = qp_sm + TQ * C_;           // TQ*8*256  (t then m)
    float* A_sm  = tm_sm + TQ * NH_ * C_;     // TQ*16*AP
    float* sc_sm = A_sm  + TQ * N_ * AP;      // TQ*8*16
    float* at_sm = sc_sm + TQ * NH_ * N_;     // TQ*16*8
    float* u_sm  = at_sm + TQ * N_ * NH_;     // TQ*8
    float* wt_sm = u_sm  + TQ * NH_;          // 128 * float4
    int*   off_sm = (int*)(wt_sm + TQ * N_ * 4); // 128 * int4

    const int tid = threadIdx.x;
    const int b   = blockIdx.y;
    const int gq0 = blockIdx.x * TQ;

    if (tid < 256) {
        // =============== COMPUTE GROUP (warps 0-7) ===============
        // ---- load q rows ----
        #pragma unroll
        for (int rep = 0; rep < TQ; rep++)
            q_sm[rep * 256 + tid] = q[(size_t)(b * Q_ + gq0 + rep) * C_ + tid];
        asm volatile("bar.sync 1, 256;" ::: "memory");

        // ---- qp = q @ wq^T + bq : thread owns channel c ----
        {
            const int c = tid;
            float acc[TQ];
            #pragma unroll
            for (int i = 0; i < TQ; i++) acc[i] = 0.f;
            const float4* wrow = (const float4*)(wq + (size_t)c * C_);
            #pragma unroll 4
            for (int k4 = 0; k4 < C_ / 4; k4++) {
                float4 w = __ldg(wrow + k4);
                #pragma unroll
                for (int i = 0; i < TQ; i++) {
                    float4 qv = *(const float4*)(q_sm + i * C_ + k4 * 4);
                    acc[i] += qv.x * w.x + qv.y * w.y + qv.z * w.z + qv.w * w.w;
                }
            }
            float bb = __ldg(bq + c);
            #pragma unroll
            for (int i = 0; i < TQ; i++) qp_sm[i * C_ + c] = acc[i] + bb;
        }
        asm volatile("bar.sync 1, 256;" ::: "memory");

        // ---- t[i][h][k] = sum_dd qp[i][h*32+dd] * wk[h*32+dd][k] ----
        {
            const int k = tid;
            #pragma unroll
            for (int h = 0; h < NH_; h++) {
                float acc[TQ];
                #pragma unroll
                for (int i = 0; i < TQ; i++) acc[i] = 0.f;
                #pragma unroll 4
                for (int d4 = 0; d4 < D_ / 4; d4++) {
                    const float* wp = wk + (size_t)(h * D_ + d4 * 4) * C_ + k;
                    float w0 = __ldg(wp);
                    float w1 = __ldg(wp + C_);
                    float w2 = __ldg(wp + 2 * C_);
                    float w3 = __ldg(wp + 3 * C_);
                    #pragma unroll
                    for (int i = 0; i < TQ; i++) {
                        float4 qv = *(const float4*)(qp_sm + i * C_ + h * D_ + d4 * 4);
                        acc[i] += qv.x * w0 + qv.y * w1 + qv.z * w2 + qv.w * w3;
                    }
                }
                #pragma unroll
                for (int i = 0; i < TQ; i++) tm_sm[(i * NH_ + h) * C_ + k] = acc[i];
            }
        }
        // ---- u[i][h] = qp_head . bk_head ----
        if (tid < TQ * NH_) {
            int i = tid / NH_, h = tid % NH_;
            float s = 0.f;
            #pragma unroll
            for (int dd = 0; dd < D_; dd++)
                s += qp_sm[i * C_ + h * D_ + dd] * __ldg(bk + h * D_ + dd);
            u_sm[tid] = s;
        }
    } else {
        // =============== GATHER GROUP (warps 8-15) ===============
        const int tr = tid - 256;

        // ---- precompute bilinear weights + tap offsets, one thread per row ----
        if (tr < TQ * N_) {
            int i  = tr >> 4, j = tr & 15;
            int rr = (gq0 + i) * N_ + j;
            int n  = rr / Q_;
            int qq = rr - n * Q_;
            float2 g = __ldg((const float2*)(ref + (size_t)((b * Q_ + qq) * N_ + n) * 2));
            float gx = ((g.x + 1.0f) * (float)W_ - 1.0f) * 0.5f;
            float gy = ((g.y + 1.0f) * (float)H_ - 1.0f) * 0.5f;
            float x0f = floorf(gx), y0f = floorf(gy);
            float fx = gx - x0f, fy = gy - y0f;
            int x0 = (int)x0f, y0 = (int)y0f;
            int x1 = x0 + 1,   y1 = y0 + 1;
            bool vx0 = (x0 >= 0) & (x0 < W_);
            bool vx1 = (x1 >= 0) & (x1 < W_);
            bool vy0 = (y0 >= 0) & (y0 < H_);
            bool vy1 = (y1 >= 0) & (y1 < H_);
            float4 w;
            w.x = (1.f - fx) * (1.f - fy);   // (x0,y0)
            w.y = fx * (1.f - fy);           // (x1,y0)
            w.z = (1.f - fx) * fy;           // (x0,y1)
            w.w = fx * fy;                   // (x1,y1)
            int4 o;
            o.x = (vy0 && vx0) ? (y0 * W_ + x0) * C_ : -1;
            o.y = (vy0 && vx1) ? (y0 * W_ + x1) * C_ : -1;
            o.z = (vy1 && vx0) ? (y1 * W_ + x0) * C_ : -1;
            o.w = (vy1 && vx1) ? (y1 * W_ + x1) * C_ : -1;
            ((float4*)wt_sm)[tr] = w;
            ((int4*)off_sm)[tr]  = o;
        }
        asm volatile("bar.sync 2, 256;" ::: "memory");

        // ---- gather: A[row][k] ----
        {
            const int k = tr;
            const float* xb = g_xt + (size_t)b * HW_ * C_;
            #pragma unroll 2
            for (int row = 0; row < TQ * N_; row++) {
                float4 w = ((const float4*)wt_sm)[row];
                int4   o = ((const int4*)off_sm)[row];
                float val = 0.f;
                if (o.x >= 0) val += w.x * __ldg(xb + o.x + k);
                if (o.y >= 0) val += w.y * __ldg(xb + o.y + k);
                if (o.z >= 0) val += w.z * __ldg(xb + o.z + k);
                if (o.w >= 0) val += w.w * __ldg(xb + o.w + k);
                A_sm[row * AP + k] = val;
            }
        }
    }
    __syncthreads();

    // ---- scores[i][h][j] = (A[i][j][:] . t[i][h][:] + u[i][h]) / sqrt(d) ----
    // 256 threads: (i, j, head-group of 4)
    if (tid < 256) {
        int i  = tid >> 5;
        int r  = tid & 31;
        int j  = r >> 1;
        int hg = (r & 1) * 4;
        float acc[4];
        #pragma unroll
        for (int hh = 0; hh < 4; hh++) acc[hh] = 0.f;
        const float4* arow = (const float4*)(A_sm + (i * N_ + j) * AP);
        #pragma unroll 4
        for (int k4 = 0; k4 < C_ / 4; k4++) {
            float4 a = arow[k4];
            #pragma unroll
            for (int hh = 0; hh < 4; hh++) {
                float4 t4 = *(const float4*)(tm_sm + (i * NH_ + hg + hh) * C_ + k4 * 4);
                acc[hh] += a.x * t4.x + a.y * t4.y + a.z * t4.z + a.w * t4.w;
            }
        }
        const float scale = 0.17677669529663687f; // 1/sqrt(32)
        #pragma unroll
        for (int hh = 0; hh < 4; hh++)
            sc_sm[(i * NH_ + hg + hh) * N_ + j] =
                (acc[hh] + u_sm[i * NH_ + hg + hh]) * scale;
    }
    __syncthreads();

    // ---- softmax over j per (i,h) : 64 threads ----
    if (tid < TQ * NH_) {
        int i = tid >> 3, h = tid & 7;
        float s[N_];
        float mx = -1e30f;
        #pragma unroll
        for (int j = 0; j < N_; j++) {
            s[j] = sc_sm[(i * NH_ + h) * N_ + j];
            mx = fmaxf(mx, s[j]);
        }
        float sum = 0.f;
        #pragma unroll
        for (int j = 0; j < N_; j++) { s[j] = expf(s[j] - mx); sum += s[j]; }
        float inv = 1.f / sum;
        #pragma unroll
        for (int j = 0; j < N_; j++)
            at_sm[(i * N_ + j) * NH_ + h] = s[j] * inv;
    }
    __syncthreads();

    // ---- m[i][h][k] = sum_j attn[i][h][j]*A[i][j][k] : 512 threads (k, i-group) ----
    {
        const int k = tid & 255;
        const int g = tid >> 8;
        #pragma unroll
        for (int ii = 0; ii < TQ / 2; ii++) {
            int i = g * (TQ / 2) + ii;
            float acc[NH_];
            #pragma unroll
            for (int h = 0; h < NH_; h++) acc[h] = 0.f;
            #pragma unroll
            for (int j = 0; j < N_; j++) {
                float a = A_sm[(i * N_ + j) * AP + k];
                float4 w0 = *(const float4*)(at_sm + (i * N_ + j) * NH_);
                float4 w1 = *(const float4*)(at_sm + (i * N_ + j) * NH_ + 4);
                acc[0] += a * w0.x; acc[1] += a * w0.y;
                acc[2] += a * w0.z; acc[3] += a * w0.w;
                acc[4] += a * w1.x; acc[5] += a * w1.y;
                acc[6] += a * w1.z; acc[7] += a * w1.w;
            }
            #pragma unroll
            for (int h = 0; h < NH_; h++) tm_sm[(i * NH_ + h) * C_ + k] = acc[h];
        }
    }
    __syncthreads();

    // ---- out[i][c] = sum_k m[i][h(c)][k]*wv[c][k] + bv[c] : 512 threads (c, i-group) ----
    {
        const int c = tid & 255;
        const int g = tid >> 8;
        const int h = c >> 5;
        float bb = __ldg(bv + c);
        float acc[TQ / 2];
        #pragma unroll
        for (int ii = 0; ii < TQ / 2; ii++) acc[ii] = bb;
        const float4* wrow = (const float4*)(wv + (size_t)c * C_);
        #pragma unroll 4
        for (int k4 = 0; k4 < C_ / 4; k4++) {
            float4 w = __ldg(wrow + k4);
            #pragma unroll
            for (int ii = 0; ii < TQ / 2; ii++) {
                int i = g * (TQ / 2) + ii;
                float4 m4 = *(const float4*)(tm_sm + (i * NH_ + h) * C_ + k4 * 4);
                acc[ii] += m4.x * w.x + m4.y * w.y + m4.z * w.z + m4.w * w.w;
            }
        }
        #pragma unroll
        for (int ii = 0; ii < TQ / 2; ii++) {
            int i = g * (TQ / 2) + ii;
            out[(size_t)(b * Q_ + gq0 + i) * C_ + c] = acc[ii];
        }
    }
}

// ---------------------------------------------------------------------------
extern "C" void kernel_launch(void* const* d_in, const int* in_sizes, int n_in,
                              void* d_out, int out_size) {
    const float* x   = (const float*)d_in[0];
    const float* q   = (const float*)d_in[1];
    const float* ref = (const float*)d_in[2];
    const float* wq  = (const float*)d_in[3];
    const float* bq  = (const float*)d_in[4];
    const float* wk  = (const float*)d_in[5];
    const float* bk  = (const float*)d_in[6];
    const float* wv  = (const float*)d_in[7];
    const float* bv  = (const float*)d_in[8];
    float* out = (float*)d_out;

    (void)in_sizes; (void)n_in; (void)out_size;

    dim3 tg((HW_ + 31) / 32, C_ / 32, B_);
    transpose_x_kernel<<<tg, dim3(32, 8)>>>(x);

    cudaFuncSetAttribute(deform_attn_kernel,
                         cudaFuncAttributeMaxDynamicSharedMemorySize, SMEM_BYTES);
    deform_attn_kernel<<<dim3(Q_ / TQ, B_), NTHREADS, SMEM_BYTES>>>(
        q, ref, wq, bq, wk, bk, wv, bv, out);
}

// round 3
// speedup vs baseline: 1.9364x; 1.2589x over previous
#include <cuda_runtime.h>

#define B_  16
#define Q_  1000
#define N_  16
#define C_  256
#define H_  100
#define W_  100
#define HW_ 10000
#define NH_ 8
#define D_  32
#define TQ  8      // queries per block
#define AP  260    // A_sm row pitch (floats)
#define NTHREADS 512

// smem layout (floats):
#define SMEM_FLOATS (2048 + 2048 + 16384 + 33280 + 1024 + 1024 + 64 + 512 + 512)
#define SMEM_BYTES  (SMEM_FLOATS * 4)

// channels-last copy of x: [B,H,W,C]
__device__ float g_xt[B_ * HW_ * C_];
// transposed weights: [k][c]
__device__ float g_wqT[C_ * C_];
__device__ float g_wvT[C_ * C_];

// ---------------------------------------------------------------------------
// Kernel 0: transpose wq, wv [c][k] -> [k][c]
// ---------------------------------------------------------------------------
__global__ void transpose_w_kernel(const float* __restrict__ wq,
                                   const float* __restrict__ wv) {
    __shared__ float tile[32][33];
    const float* src = blockIdx.z == 0 ? wq : wv;
    float* dst = blockIdx.z == 0 ? g_wqT : g_wvT;
    int c0 = blockIdx.x * 32;   // row dim of src (c)
    int k0 = blockIdx.y * 32;   // col dim of src (k)
    int tx = threadIdx.x, ty = threadIdx.y;   // 32x8
    #pragma unroll
    for (int dy = 0; dy < 32; dy += 8)
        tile[ty + dy][tx] = src[(size_t)(c0 + ty + dy) * C_ + k0 + tx];
    __syncthreads();
    #pragma unroll
    for (int dy = 0; dy < 32; dy += 8)
        dst[(size_t)(k0 + ty + dy) * C_ + c0 + tx] = tile[tx][ty + dy];
}

// ---------------------------------------------------------------------------
// Kernel 1: transpose x [B,C,HW] -> g_xt [B,HW,C]
// ---------------------------------------------------------------------------
__global__ void transpose_x_kernel(const float* __restrict__ x) {
    __shared__ float tile[32][33];
    int b  = blockIdx.z;
    int p0 = blockIdx.x * 32;   // HW dim
    int c0 = blockIdx.y * 32;   // C dim
    int tx = threadIdx.x;
    int ty = threadIdx.y;       // 32x8 threads

    #pragma unroll
    for (int dy = 0; dy < 32; dy += 8) {
        int c = c0 + ty + dy;
        int p = p0 + tx;
        float v = 0.f;
        if (p < HW_) v = x[(size_t)(b * C_ + c) * HW_ + p];
        tile[ty + dy][tx] = v;
    }
    __syncthreads();
    #pragma unroll
    for (int dy = 0; dy < 32; dy += 8) {
        int p = p0 + ty + dy;
        int c = c0 + tx;
        if (p < HW_) g_xt[(size_t)(b * HW_ + p) * C_ + c] = tile[tx][ty + dy];
    }
}

// ---------------------------------------------------------------------------
// Kernel 2: fused deformable attention. One block = TQ queries of one batch.
// 512 threads. Warps 0-7: projections. Warps 8-15: bilinear gather.
// ---------------------------------------------------------------------------
__global__ __launch_bounds__(NTHREADS, 1)
void deform_attn_kernel(const float* __restrict__ q,
                        const float* __restrict__ ref,
                        const float* __restrict__ bq,
                        const float* __restrict__ wk, const float* __restrict__ bk,
                        const float* __restrict__ bv,
                        float* __restrict__ out) {
    extern __shared__ float sm[];
    float* q_sm  = sm;                        // TQ*256
    float* qp_sm = q_sm  + TQ * C_;           // TQ*256
    float* tm_sm = qp_sm + TQ * C_;           // TQ*8*256  (t then m)
    float* A_sm  = tm_sm + TQ * NH_ * C_;     // TQ*16*AP
    float* sc_sm = A_sm  + TQ * N_ * AP;      // TQ*8*16
    float* at_sm = sc_sm + TQ * NH_ * N_;     // TQ*16*8
    float* u_sm  = at_sm + TQ * N_ * NH_;     // TQ*8
    float* wt_sm = u_sm  + TQ * NH_;          // 128 * float4
    int*   off_sm = (int*)(wt_sm + TQ * N_ * 4); // 128 * int4

    const int tid = threadIdx.x;
    const int b   = blockIdx.y;
    const int gq0 = blockIdx.x * TQ;

    if (tid < 256) {
        // =============== COMPUTE GROUP (warps 0-7) ===============
        // ---- load q rows (coalesced) ----
        #pragma unroll
        for (int rep = 0; rep < TQ; rep++)
            q_sm[rep * 256 + tid] = q[(size_t)(b * Q_ + gq0 + rep) * C_ + tid];
        asm volatile("bar.sync 1, 256;" ::: "memory");

        // ---- qp = q @ wq^T + bq : thread owns channel c, coalesced wqT reads ----
        {
            const int c = tid;
            float acc[TQ];
            #pragma unroll
            for (int i = 0; i < TQ; i++) acc[i] = 0.f;
            #pragma unroll 4
            for (int k4 = 0; k4 < C_ / 4; k4++) {
                const float* wp = g_wqT + (size_t)(k4 * 4) * C_ + c;
                float w0 = __ldg(wp);
                float w1 = __ldg(wp + C_);
                float w2 = __ldg(wp + 2 * C_);
                float w3 = __ldg(wp + 3 * C_);
                #pragma unroll
                for (int i = 0; i < TQ; i++) {
                    float4 qv = *(const float4*)(q_sm + i * C_ + k4 * 4);
                    acc[i] += qv.x * w0 + qv.y * w1 + qv.z * w2 + qv.w * w3;
                }
            }
            float bb = __ldg(bq + c);
            #pragma unroll
            for (int i = 0; i < TQ; i++) qp_sm[i * C_ + c] = acc[i] + bb;
        }
        asm volatile("bar.sync 1, 256;" ::: "memory");

        // ---- t[i][h][k] = sum_dd qp[i][h*32+dd] * wk[h*32+dd][k] (coalesced) ----
        {
            const int k = tid;
            #pragma unroll
            for (int h = 0; h < NH_; h++) {
                float acc[TQ];
                #pragma unroll
                for (int i = 0; i < TQ; i++) acc[i] = 0.f;
                #pragma unroll 4
                for (int d4 = 0; d4 < D_ / 4; d4++) {
                    const float* wp = wk + (size_t)(h * D_ + d4 * 4) * C_ + k;
                    float w0 = __ldg(wp);
                    float w1 = __ldg(wp + C_);
                    float w2 = __ldg(wp + 2 * C_);
                    float w3 = __ldg(wp + 3 * C_);
                    #pragma unroll
                    for (int i = 0; i < TQ; i++) {
                        float4 qv = *(const float4*)(qp_sm + i * C_ + h * D_ + d4 * 4);
                        acc[i] += qv.x * w0 + qv.y * w1 + qv.z * w2 + qv.w * w3;
                    }
                }
                #pragma unroll
                for (int i = 0; i < TQ; i++) tm_sm[(i * NH_ + h) * C_ + k] = acc[i];
            }
        }
        // ---- u[i][h] = qp_head . bk_head ----
        if (tid < TQ * NH_) {
            int i = tid / NH_, h = tid % NH_;
            float s = 0.f;
            #pragma unroll
            for (int dd = 0; dd < D_; dd++)
                s += qp_sm[i * C_ + h * D_ + dd] * __ldg(bk + h * D_ + dd);
            u_sm[tid] = s;
        }
    } else {
        // =============== GATHER GROUP (warps 8-15) ===============
        const int tr = tid - 256;

        // ---- precompute bilinear weights + tap offsets, one thread per row ----
        if (tr < TQ * N_) {
            int i  = tr >> 4, j = tr & 15;
            int rr = (gq0 + i) * N_ + j;
            int n  = rr / Q_;
            int qq = rr - n * Q_;
            float2 g = __ldg((const float2*)(ref + (size_t)((b * Q_ + qq) * N_ + n) * 2));
            float gx = ((g.x + 1.0f) * (float)W_ - 1.0f) * 0.5f;
            float gy = ((g.y + 1.0f) * (float)H_ - 1.0f) * 0.5f;
            float x0f = floorf(gx), y0f = floorf(gy);
            float fx = gx - x0f, fy = gy - y0f;
            int x0 = (int)x0f, y0 = (int)y0f;
            int x1 = x0 + 1,   y1 = y0 + 1;
            bool vx0 = (x0 >= 0) & (x0 < W_);
            bool vx1 = (x1 >= 0) & (x1 < W_);
            bool vy0 = (y0 >= 0) & (y0 < H_);
            bool vy1 = (y1 >= 0) & (y1 < H_);
            float4 w;
            w.x = (1.f - fx) * (1.f - fy);
            w.y = fx * (1.f - fy);
            w.z = (1.f - fx) * fy;
            w.w = fx * fy;
            int4 o;
            o.x = (vy0 && vx0) ? (y0 * W_ + x0) * C_ : -1;
            o.y = (vy0 && vx1) ? (y0 * W_ + x1) * C_ : -1;
            o.z = (vy1 && vx0) ? (y1 * W_ + x0) * C_ : -1;
            o.w = (vy1 && vx1) ? (y1 * W_ + x1) * C_ : -1;
            ((float4*)wt_sm)[tr] = w;
            ((int4*)off_sm)[tr]  = o;
        }
        asm volatile("bar.sync 2, 256;" ::: "memory");

        // ---- gather: A[row][k] (each tap coalesced 128B per warp) ----
        {
            const int k = tr;
            const float* xb = g_xt + (size_t)b * HW_ * C_;
            #pragma unroll 2
            for (int row = 0; row < TQ * N_; row++) {
                float4 w = ((const float4*)wt_sm)[row];
                int4   o = ((const int4*)off_sm)[row];
                float val = 0.f;
                if (o.x >= 0) val += w.x * __ldg(xb + o.x + k);
                if (o.y >= 0) val += w.y * __ldg(xb + o.y + k);
                if (o.z >= 0) val += w.z * __ldg(xb + o.z + k);
                if (o.w >= 0) val += w.w * __ldg(xb + o.w + k);
                A_sm[row * AP + k] = val;
            }
        }
    }
    __syncthreads();

    // ---- scores[i][h][j] = (A[i][j][:] . t[i][h][:] + u[i][h]) / sqrt(d) ----
    if (tid < 256) {
        int i  = tid >> 5;
        int r  = tid & 31;
        int j  = r >> 1;
        int hg = (r & 1) * 4;
        float acc[4];
        #pragma unroll
        for (int hh = 0; hh < 4; hh++) acc[hh] = 0.f;
        const float4* arow = (const float4*)(A_sm + (i * N_ + j) * AP);
        #pragma unroll 4
        for (int k4 = 0; k4 < C_ / 4; k4++) {
            float4 a = arow[k4];
            #pragma unroll
            for (int hh = 0; hh < 4; hh++) {
                float4 t4 = *(const float4*)(tm_sm + (i * NH_ + hg + hh) * C_ + k4 * 4);
                acc[hh] += a.x * t4.x + a.y * t4.y + a.z * t4.z + a.w * t4.w;
            }
        }
        const float scale = 0.17677669529663687f; // 1/sqrt(32)
        #pragma unroll
        for (int hh = 0; hh < 4; hh++)
            sc_sm[(i * NH_ + hg + hh) * N_ + j] =
                (acc[hh] + u_sm[i * NH_ + hg + hh]) * scale;
    }
    __syncthreads();

    // ---- softmax over j per (i,h) : 64 threads ----
    if (tid < TQ * NH_) {
        int i = tid >> 3, h = tid & 7;
        float s[N_];
        float mx = -1e30f;
        #pragma unroll
        for (int j = 0; j < N_; j++) {
            s[j] = sc_sm[(i * NH_ + h) * N_ + j];
            mx = fmaxf(mx, s[j]);
        }
        float sum = 0.f;
        #pragma unroll
        for (int j = 0; j < N_; j++) { s[j] = expf(s[j] - mx); sum += s[j]; }
        float inv = 1.f / sum;
        #pragma unroll
        for (int j = 0; j < N_; j++)
            at_sm[(i * N_ + j) * NH_ + h] = s[j] * inv;
    }
    __syncthreads();

    // ---- m[i][h][k] = sum_j attn[i][h][j]*A[i][j][k] : 512 threads (k, i-group) ----
    {
        const int k = tid & 255;
        const int g = tid >> 8;
        #pragma unroll
        for (int ii = 0; ii < TQ / 2; ii++) {
            int i = g * (TQ / 2) + ii;
            float acc[NH_];
            #pragma unroll
            for (int h = 0; h < NH_; h++) acc[h] = 0.f;
            #pragma unroll
            for (int j = 0; j < N_; j++) {
                float a = A_sm[(i * N_ + j) * AP + k];
                float4 w0 = *(const float4*)(at_sm + (i * N_ + j) * NH_);
                float4 w1 = *(const float4*)(at_sm + (i * N_ + j) * NH_ + 4);
                acc[0] += a * w0.x; acc[1] += a * w0.y;
                acc[2] += a * w0.z; acc[3] += a * w0.w;
                acc[4] += a * w1.x; acc[5] += a * w1.y;
                acc[6] += a * w1.z; acc[7] += a * w1.w;
            }
            #pragma unroll
            for (int h = 0; h < NH_; h++) tm_sm[(i * NH_ + h) * C_ + k] = acc[h];
        }
    }
    __syncthreads();

    // ---- out[i][c] = sum_k m[i][h(c)][k]*wvT[k][c] + bv[c] : 512 thr (c, i-grp) ----
    {
        const int c = tid & 255;
        const int g = tid >> 8;
        const int h = c >> 5;           // constant within a warp
        float bb = __ldg(bv + c);
        float acc[TQ / 2];
        #pragma unroll
        for (int ii = 0; ii < TQ / 2; ii++) acc[ii] = bb;
        #pragma unroll 4
        for (int k4 = 0; k4 < C_ / 4; k4++) {
            const float* wp = g_wvT + (size_t)(k4 * 4) * C_ + c;
            float w0 = __ldg(wp);
            float w1 = __ldg(wp + C_);
            float w2 = __ldg(wp + 2 * C_);
            float w3 = __ldg(wp + 3 * C_);
            #pragma unroll
            for (int ii = 0; ii < TQ / 2; ii++) {
                int i = g * (TQ / 2) + ii;
                float4 m4 = *(const float4*)(tm_sm + (i * NH_ + h) * C_ + k4 * 4);
                acc[ii] += m4.x * w0 + m4.y * w1 + m4.z * w2 + m4.w * w3;
            }
        }
        #pragma unroll
        for (int ii = 0; ii < TQ / 2; ii++) {
            int i = g * (TQ / 2) + ii;
            out[(size_t)(b * Q_ + gq0 + i) * C_ + c] = acc[ii];
        }
    }
}

// ---------------------------------------------------------------------------
extern "C" void kernel_launch(void* const* d_in, const int* in_sizes, int n_in,
                              void* d_out, int out_size) {
    const float* x   = (const float*)d_in[0];
    const float* q   = (const float*)d_in[1];
    const float* ref = (const float*)d_in[2];
    const float* wq  = (const float*)d_in[3];
    const float* bq  = (const float*)d_in[4];
    const float* wk  = (const float*)d_in[5];
    const float* bk  = (const float*)d_in[6];
    const float* wv  = (const float*)d_in[7];
    const float* bv  = (const float*)d_in[8];
    float* out = (float*)d_out;

    (void)in_sizes; (void)n_in; (void)out_size;

    dim3 wg(C_ / 32, C_ / 32, 2);
    transpose_w_kernel<<<wg, dim3(32, 8)>>>(wq, wv);

    dim3 tg((HW_ + 31) / 32, C_ / 32, B_);
    transpose_x_kernel<<<tg, dim3(32, 8)>>>(x);

    cudaFuncSetAttribute(deform_attn_kernel,
                         cudaFuncAttributeMaxDynamicSharedMemorySize, SMEM_BYTES);
    deform_attn_kernel<<<dim3(Q_ / TQ, B_), NTHREADS, SMEM_BYTES>>>(
        q, ref, bq, wk, bk, bv, out);
}

// round 4
// speedup vs baseline: 2.9327x; 1.5145x over previous
#include <cuda_runtime.h>
#include <cuda_fp16.h>

#define B_  16
#define Q_  1000
#define N_  16
#define C_  256
#define H_  100
#define W_  100
#define HW_ 10000
#define NH_ 8
#define D_  32
#define TQ  8
#define AP2 260        // A_sm row pitch in halves (520B/row: 8B-aligned, conflict-free)
#define NTHREADS 512

// ---- dynamic smem byte offsets ----
#define OFF_A    0
#define SZ_A     (TQ*N_*AP2*2)          // 66560  half A[128][260]
#define OFF_TM   (OFF_A + SZ_A)         // 66560  half tm[8][8][256] (t then m)
#define SZ_TM    (TQ*NH_*C_*2)          // 32768
#define OFF_QP   (OFF_TM + SZ_TM)       // 99328  half qp[8][256]
#define SZ_QP    (TQ*C_*2)              // 4096
#define OFF_QU   (OFF_QP + SZ_QP)       // 103424 union: float q[8][256] | {half sc, half at}
#define SZ_QU    (TQ*C_*4)              // 8192
#define OFF_SC   OFF_QU                 // half sc[8][8][16] = 2048B
#define OFF_AT   (OFF_QU + 2048)        // half at[8][16][8] = 2048B
#define OFF_U    (OFF_QU + SZ_QU)       // 111616 float u[64]
#define SZ_U     (TQ*NH_*4)             // 256
#define OFF_WT   (OFF_U + SZ_U)         // 111872 float4 wt[128]
#define SZ_WT    (TQ*N_*16)             // 2048
#define OFF_OY   (OFF_WT + SZ_WT)       // 113920 int2 oy[128]
#define SZ_OY    (TQ*N_*8)              // 1024
#define OFF_OX   (OFF_OY + SZ_OY)       // 114944 ushort2 ox[128]
#define SZ_OX    (TQ*N_*4)              // 512
#define SMEM_BYTES (OFF_OX + SZ_OX)     // 115456 -> 2 blocks/SM

// channels-last fp16 copy of x: [B,H,W,C]
__device__ __half g_xt[B_ * HW_ * C_];
// transposed weights: [k][c]
__device__ float g_wqT[C_ * C_];
__device__ float g_wvT[C_ * C_];

// ---------------------------------------------------------------------------
// Kernel 0: transpose wq, wv [c][k] -> [k][c]
// ---------------------------------------------------------------------------
__global__ void transpose_w_kernel(const float* __restrict__ wq,
                                   const float* __restrict__ wv) {
    __shared__ float tile[32][33];
    const float* src = blockIdx.z == 0 ? wq : wv;
    float* dst = blockIdx.z == 0 ? g_wqT : g_wvT;
    int c0 = blockIdx.x * 32;
    int k0 = blockIdx.y * 32;
    int tx = threadIdx.x, ty = threadIdx.y;   // 32x8
    #pragma unroll
    for (int dy = 0; dy < 32; dy += 8)
        tile[ty + dy][tx] = src[(size_t)(c0 + ty + dy) * C_ + k0 + tx];
    __syncthreads();
    #pragma unroll
    for (int dy = 0; dy < 32; dy += 8)
        dst[(size_t)(k0 + ty + dy) * C_ + c0 + tx] = tile[tx][ty + dy];
}

// ---------------------------------------------------------------------------
// Kernel 1: transpose x [B,C,HW] -> g_xt [B,HW,C] (fp16)
// ---------------------------------------------------------------------------
__global__ void transpose_x_kernel(const float* __restrict__ x) {
    __shared__ float tile[32][33];
    int b  = blockIdx.z;
    int p0 = blockIdx.x * 32;   // HW dim
    int c0 = blockIdx.y * 32;   // C dim
    int tx = threadIdx.x;
    int ty = threadIdx.y;       // 32x8 threads

    #pragma unroll
    for (int dy = 0; dy < 32; dy += 8) {
        int c = c0 + ty + dy;
        int p = p0 + tx;
        float v = 0.f;
        if (p < HW_) v = x[(size_t)(b * C_ + c) * HW_ + p];
        tile[ty + dy][tx] = v;
    }
    __syncthreads();
    #pragma unroll
    for (int dy = 0; dy < 32; dy += 8) {
        int p = p0 + ty + dy;
        int c = c0 + tx;
        if (p < HW_)
            g_xt[(size_t)(b * HW_ + p) * C_ + c] = __float2half_rn(tile[tx][ty + dy]);
    }
}

// ---------------------------------------------------------------------------
// Kernel 2: fused deformable attention. 512 threads, 2 blocks/SM.
// Warps 0-7: projections. Warps 8-15: bilinear gather.
// ---------------------------------------------------------------------------
__global__ __launch_bounds__(NTHREADS, 2)
void deform_attn_kernel(const float* __restrict__ q,
                        const float* __restrict__ ref,
                        const float* __restrict__ bq,
                        const float* __restrict__ wk, const float* __restrict__ bk,
                        const float* __restrict__ bv,
                        float* __restrict__ out) {
    extern __shared__ char smc[];
    __half* A_sm   = (__half*)(smc + OFF_A);
    __half* tm_sm  = (__half*)(smc + OFF_TM);
    __half* qp_sm  = (__half*)(smc + OFF_QP);
    float*  q_sm   = (float*)(smc + OFF_QU);
    __half* sc_sm  = (__half*)(smc + OFF_SC);
    __half* at_sm  = (__half*)(smc + OFF_AT);
    float*  u_sm   = (float*)(smc + OFF_U);
    float4* wt_sm  = (float4*)(smc + OFF_WT);
    int2*   oy_sm  = (int2*)(smc + OFF_OY);
    ushort2* ox_sm = (ushort2*)(smc + OFF_OX);

    const int tid = threadIdx.x;
    const int b   = blockIdx.y;
    const int gq0 = blockIdx.x * TQ;

    if (tid < 256) {
        // =============== COMPUTE GROUP (warps 0-7) ===============
        #pragma unroll
        for (int rep = 0; rep < TQ; rep++)
            q_sm[rep * 256 + tid] = q[(size_t)(b * Q_ + gq0 + rep) * C_ + tid];
        asm volatile("bar.sync 1, 256;" ::: "memory");

        // ---- qp = q @ wq^T + bq : thread owns channel c (coalesced wqT) ----
        {
            const int c = tid;
            float acc[TQ];
            #pragma unroll
            for (int i = 0; i < TQ; i++) acc[i] = 0.f;
            #pragma unroll 2
            for (int k4 = 0; k4 < C_ / 4; k4++) {
                const float* wp = g_wqT + (size_t)(k4 * 4) * C_ + c;
                float w0 = __ldg(wp);
                float w1 = __ldg(wp + C_);
                float w2 = __ldg(wp + 2 * C_);
                float w3 = __ldg(wp + 3 * C_);
                #pragma unroll
                for (int i = 0; i < TQ; i++) {
                    float4 qv = *(const float4*)(q_sm + i * C_ + k4 * 4);
                    acc[i] += qv.x * w0 + qv.y * w1 + qv.z * w2 + qv.w * w3;
                }
            }
            float bb = __ldg(bq + c);
            #pragma unroll
            for (int i = 0; i < TQ; i++)
                qp_sm[i * C_ + c] = __float2half_rn(acc[i] + bb);
        }
        asm volatile("bar.sync 1, 256;" ::: "memory");

        // ---- t[i][h][k] = sum_dd qp[i][h*32+dd] * wk[h*32+dd][k] ----
        {
            const int k = tid;
            #pragma unroll
            for (int h = 0; h < NH_; h++) {
                float acc[TQ];
                #pragma unroll
                for (int i = 0; i < TQ; i++) acc[i] = 0.f;
                #pragma unroll 2
                for (int d4 = 0; d4 < D_ / 4; d4++) {
                    const float* wp = wk + (size_t)(h * D_ + d4 * 4) * C_ + k;
                    float w0 = __ldg(wp);
                    float w1 = __ldg(wp + C_);
                    float w2 = __ldg(wp + 2 * C_);
                    float w3 = __ldg(wp + 3 * C_);
                    #pragma unroll
                    for (int i = 0; i < TQ; i++) {
                        const __half2* qpp =
                            (const __half2*)(qp_sm + i * C_ + h * D_ + d4 * 4);
                        float2 q01 = __half22float2(qpp[0]);
                        float2 q23 = __half22float2(qpp[1]);
                        acc[i] += q01.x * w0 + q01.y * w1 + q23.x * w2 + q23.y * w3;
                    }
                }
                #pragma unroll
                for (int i = 0; i < TQ; i++)
                    tm_sm[(i * NH_ + h) * C_ + k] = __float2half_rn(acc[i]);
            }
        }
        // ---- u[i][h] = qp_head . bk_head ----
        if (tid < TQ * NH_) {
            int i = tid / NH_, h = tid % NH_;
            float s = 0.f;
            #pragma unroll
            for (int dd = 0; dd < D_; dd++)
                s += __half2float(qp_sm[i * C_ + h * D_ + dd]) * __ldg(bk + h * D_ + dd);
            u_sm[tid] = s;
        }
    } else {
        // =============== GATHER GROUP (warps 8-15) ===============
        const int tr = tid - 256;

        if (tr < TQ * N_) {
            int i  = tr >> 4, j = tr & 15;
            int rr = (gq0 + i) * N_ + j;
            int n  = rr / Q_;
            int qq = rr - n * Q_;
            float2 g = __ldg((const float2*)(ref + (size_t)((b * Q_ + qq) * N_ + n) * 2));
            float gx = ((g.x + 1.0f) * (float)W_ - 1.0f) * 0.5f;
            float gy = ((g.y + 1.0f) * (float)H_ - 1.0f) * 0.5f;
            float x0f = floorf(gx), y0f = floorf(gy);
            float fx = gx - x0f, fy = gy - y0f;
            int x0 = (int)x0f, y0 = (int)y0f;
            int x1 = x0 + 1,   y1 = y0 + 1;
            bool vx0 = (x0 >= 0) & (x0 < W_);
            bool vx1 = (x1 >= 0) & (x1 < W_);
            bool vy0 = (y0 >= 0) & (y0 < H_);
            bool vy1 = (y1 >= 0) & (y1 < H_);
            float4 w;
            w.x = (vx0 && vy0) ? (1.f - fx) * (1.f - fy) : 0.f;  // (x0,y0)
            w.y = (vx1 && vy0) ? fx * (1.f - fy)         : 0.f;  // (x1,y0)
            w.z = (vx0 && vy1) ? (1.f - fx) * fy         : 0.f;  // (x0,y1)
            w.w = (vx1 && vy1) ? fx * fy                 : 0.f;  // (x1,y1)
            int x0c = min(max(x0, 0), W_ - 1);
            int x1c = min(max(x1, 0), W_ - 1);
            int y0c = min(max(y0, 0), H_ - 1);
            int y1c = min(max(y1, 0), H_ - 1);
            wt_sm[tr] = w;
            oy_sm[tr] = make_int2(y0c * W_ * C_, y1c * W_ * C_);
            ox_sm[tr] = make_ushort2((unsigned short)(x0c * C_),
                                     (unsigned short)(x1c * C_));
        }
        asm volatile("bar.sync 2, 256;" ::: "memory");

        // ---- gather: A[row][k], branch-free (weights zeroed, offsets clamped) ----
        {
            const int k = tr;
            const __half* xb = g_xt + (size_t)b * HW_ * C_;
            #pragma unroll 2
            for (int row = 0; row < TQ * N_; row++) {
                float4  w  = wt_sm[row];
                int2    oy = oy_sm[row];
                ushort2 ox = ox_sm[row];
                float val =
                    w.x * __half2float(__ldg(xb + oy.x + ox.x + k)) +
                    w.y * __half2float(__ldg(xb + oy.x + ox.y + k)) +
                    w.z * __half2float(__ldg(xb + oy.y + ox.x + k)) +
                    w.w * __half2float(__ldg(xb + oy.y + ox.y + k));
                A_sm[row * AP2 + k] = __float2half_rn(val);
            }
        }
    }
    __syncthreads();

    // ---- scores[i][h][j] = (A[i][j][:] . t[i][h][:] + u[i][h]) / sqrt(d) ----
    if (tid < 256) {
        int i  = tid >> 5;
        int r  = tid & 31;
        int j  = r >> 1;
        int hg = (r & 1) * 4;
        float acc[4];
        #pragma unroll
        for (int hh = 0; hh < 4; hh++) acc[hh] = 0.f;
        #pragma unroll 2
        for (int k4 = 0; k4 < C_ / 4; k4++) {
            const __half2* ap = (const __half2*)(A_sm + (i * N_ + j) * AP2 + k4 * 4);
            float2 a01 = __half22float2(ap[0]);
            float2 a23 = __half22float2(ap[1]);
            #pragma unroll
            for (int hh = 0; hh < 4; hh++) {
                const __half2* tp =
                    (const __half2*)(tm_sm + (i * NH_ + hg + hh) * C_ + k4 * 4);
                float2 t01 = __half22float2(tp[0]);
                float2 t23 = __half22float2(tp[1]);
                acc[hh] += a01.x * t01.x + a01.y * t01.y +
                           a23.x * t23.x + a23.y * t23.y;
            }
        }
        const float scale = 0.17677669529663687f; // 1/sqrt(32)
        #pragma unroll
        for (int hh = 0; hh < 4; hh++)
            sc_sm[(i * NH_ + hg + hh) * N_ + j] =
                __float2half_rn((acc[hh] + u_sm[i * NH_ + hg + hh]) * scale);
    }
    __syncthreads();

    // ---- softmax over j per (i,h) : 64 threads ----
    if (tid < TQ * NH_) {
        int i = tid >> 3, h = tid & 7;
        float s[N_];
        float mx = -1e30f;
        #pragma unroll
        for (int j = 0; j < N_; j++) {
            s[j] = __half2float(sc_sm[(i * NH_ + h) * N_ + j]);
            mx = fmaxf(mx, s[j]);
        }
        float sum = 0.f;
        #pragma unroll
        for (int j = 0; j < N_; j++) { s[j] = expf(s[j] - mx); sum += s[j]; }
        float inv = 1.f / sum;
        #pragma unroll
        for (int j = 0; j < N_; j++)
            at_sm[(i * N_ + j) * NH_ + h] = __float2half_rn(s[j] * inv);
    }
    __syncthreads();

    // ---- m[i][h][k] = sum_j attn[i][h][j]*A[i][j][k] : 512 threads (k, i-group) ----
    {
        const int k = tid & 255;
        const int g = tid >> 8;
        #pragma unroll
        for (int ii = 0; ii < TQ / 2; ii++) {
            int i = g * (TQ / 2) + ii;
            float acc[NH_];
            #pragma unroll
            for (int h = 0; h < NH_; h++) acc[h] = 0.f;
            #pragma unroll
            for (int j = 0; j < N_; j++) {
                float a = __half2float(A_sm[(i * N_ + j) * AP2 + k]);
                const __half2* atp = (const __half2*)(at_sm + (i * N_ + j) * NH_);
                float2 p0 = __half22float2(atp[0]);
                float2 p1 = __half22float2(atp[1]);
                float2 p2 = __half22float2(atp[2]);
                float2 p3 = __half22float2(atp[3]);
                acc[0] += a * p0.x; acc[1] += a * p0.y;
                acc[2] += a * p1.x; acc[3] += a * p1.y;
                acc[4] += a * p2.x; acc[5] += a * p2.y;
                acc[6] += a * p3.x; acc[7] += a * p3.y;
            }
            #pragma unroll
            for (int h = 0; h < NH_; h++)
                tm_sm[(i * NH_ + h) * C_ + k] = __float2half_rn(acc[h]);
        }
    }
    __syncthreads();

    // ---- out[i][c] = sum_k m[i][h(c)][k]*wvT[k][c] + bv[c] : 512 thr (c, i-grp) ----
    {
        const int c = tid & 255;
        const int g = tid >> 8;
        const int h = c >> 5;           // constant within a warp
        float bb = __ldg(bv + c);
        float acc[TQ / 2];
        #pragma unroll
        for (int ii = 0; ii < TQ / 2; ii++) acc[ii] = bb;
        #pragma unroll 2
        for (int k4 = 0; k4 < C_ / 4; k4++) {
            const float* wp = g_wvT + (size_t)(k4 * 4) * C_ + c;
            float w0 = __ldg(wp);
            float w1 = __ldg(wp + C_);
            float w2 = __ldg(wp + 2 * C_);
            float w3 = __ldg(wp + 3 * C_);
            #pragma unroll
            for (int ii = 0; ii < TQ / 2; ii++) {
                int i = g * (TQ / 2) + ii;
                const __half2* mp =
                    (const __half2*)(tm_sm + (i * NH_ + h) * C_ + k4 * 4);
                float2 m01 = __half22float2(mp[0]);
                float2 m23 = __half22float2(mp[1]);
                acc[ii] += m01.x * w0 + m01.y * w1 + m23.x * w2 + m23.y * w3;
            }
        }
        #pragma unroll
        for (int ii = 0; ii < TQ / 2; ii++) {
            int i = g * (TQ / 2) + ii;
            out[(size_t)(b * Q_ + gq0 + i) * C_ + c] = acc[ii];
        }
    }
}

// ---------------------------------------------------------------------------
extern "C" void kernel_launch(void* const* d_in, const int* in_sizes, int n_in,
                              void* d_out, int out_size) {
    const float* x   = (const float*)d_in[0];
    const float* q   = (const float*)d_in[1];
    const float* ref = (const float*)d_in[2];
    const float* wq  = (const float*)d_in[3];
    const float* bq  = (const float*)d_in[4];
    const float* wk  = (const float*)d_in[5];
    const float* bk  = (const float*)d_in[6];
    const float* wv  = (const float*)d_in[7];
    const float* bv  = (const float*)d_in[8];
    float* out = (float*)d_out;

    (void)in_sizes; (void)n_in; (void)out_size;

    dim3 wg(C_ / 32, C_ / 32, 2);
    transpose_w_kernel<<<wg, dim3(32, 8)>>>(wq, wv);

    dim3 tg((HW_ + 31) / 32, C_ / 32, B_);
    transpose_x_kernel<<<tg, dim3(32, 8)>>>(x);

    cudaFuncSetAttribute(deform_attn_kernel,
                         cudaFuncAttributeMaxDynamicSharedMemorySize, SMEM_BYTES);
    deform_attn_kernel<<<dim3(Q_ / TQ, B_), NTHREADS, SMEM_BYTES>>>(
        q, ref, bq, wk, bk, bv, out);
}